// round 9
// baseline (speedup 1.0000x reference)
#include <cuda_runtime.h>
#include <cstdint>
#include <math.h>

// Problem dims (fixed by the reference)
#define BB 2048
#define SS 50
#define EE 256
#define HH 512
#define G4 (4*HH)     // 2048
#define WW 256
#define LL 50

// JAX threefry mode: 1 = partitionable (default since jax 0.4.36), 0 = legacy
#define PARTITIONABLE 1

// ---------------- scratch (static device globals; no allocation) ----------------
__device__ __align__(16) float g_X[SS*BB*EE];        // gathered embeddings, [s][b][e]
__device__ __align__(16) float g_gates[SS*BB*G4];    // encoder pre-activations / per-step gates
__device__ __align__(16) float g_enc[BB*SS*HH];      // encoder hidden states [b][s][h]
__device__ __align__(16) float g_blend1[BB*SS*WW];   // W1 @ enc_states, [b][s][w]
__device__ __align__(16) float g_gdec[BB*G4];        // decoder gates
__device__ __align__(16) float g_h[BB*HH];
__device__ __align__(16) float g_c[BB*HH];
__device__ __align__(16) float g_blend2[BB*WW];
__device__ __align__(16) float g_bias_enc[G4];
__device__ __align__(16) float g_bias_dec[G4];
__device__ unsigned char g_mask[BB*SS];

// ---------------- Threefry-2x32-20 (exact JAX algorithm) ----------------
__device__ __forceinline__ uint32_t rotl32(uint32_t v, int r) {
    return (v << r) | (v >> (32 - r));
}

__device__ __forceinline__ void tf2x32(uint32_t k0, uint32_t k1,
                                       uint32_t& x0, uint32_t& x1) {
    const uint32_t ks2 = k0 ^ k1 ^ 0x1BD11BDAu;
    x0 += k0; x1 += k1;
    x0 += x1; x1 = rotl32(x1, 13); x1 ^= x0;
    x0 += x1; x1 = rotl32(x1, 15); x1 ^= x0;
    x0 += x1; x1 = rotl32(x1, 26); x1 ^= x0;
    x0 += x1; x1 = rotl32(x1,  6); x1 ^= x0;
    x0 += k1; x1 += ks2 + 1u;
    x0 += x1; x1 = rotl32(x1, 17); x1 ^= x0;
    x0 += x1; x1 = rotl32(x1, 29); x1 ^= x0;
    x0 += x1; x1 = rotl32(x1, 16); x1 ^= x0;
    x0 += x1; x1 = rotl32(x1, 24); x1 ^= x0;
    x0 += ks2; x1 += k0 + 2u;
    x0 += x1; x1 = rotl32(x1, 13); x1 ^= x0;
    x0 += x1; x1 = rotl32(x1, 15); x1 ^= x0;
    x0 += x1; x1 = rotl32(x1, 26); x1 ^= x0;
    x0 += x1; x1 = rotl32(x1,  6); x1 ^= x0;
    x0 += k0; x1 += k1 + 3u;
    x0 += x1; x1 = rotl32(x1, 17); x1 ^= x0;
    x0 += x1; x1 = rotl32(x1, 29); x1 ^= x0;
    x0 += x1; x1 = rotl32(x1, 16); x1 ^= x0;
    x0 += x1; x1 = rotl32(x1, 24); x1 ^= x0;
    x0 += k1; x1 += ks2 + 4u;
    x0 += x1; x1 = rotl32(x1, 13); x1 ^= x0;
    x0 += x1; x1 = rotl32(x1, 15); x1 ^= x0;
    x0 += x1; x1 = rotl32(x1, 26); x1 ^= x0;
    x0 += x1; x1 = rotl32(x1,  6); x1 ^= x0;
    x0 += ks2; x1 += k0 + 5u;
}

// key_k = split(key(42), 50)[k]
__device__ __forceinline__ void derive_key(int step, uint32_t& K0, uint32_t& K1) {
#if PARTITIONABLE
    uint32_t a = 0u, b = (uint32_t)step;      // iota64 step -> (hi=0, lo=step)
    tf2x32(0u, 42u, a, b);
    K0 = a; K1 = b;
#else
    // legacy: out = concat(o0, o1) of threefry over iota(100) split into halves
    const int la = (step < 25) ? 2*step : 2*step - 50;
    uint32_t a0 = (uint32_t)la,     a1 = (uint32_t)(la + 50);
    uint32_t b0 = (uint32_t)(la+1), b1 = (uint32_t)(la + 51);
    tf2x32(0u, 42u, a0, a1);
    tf2x32(0u, 42u, b0, b1);
    if (step < 25) { K0 = a0; K1 = b0; } else { K0 = a1; K1 = b1; }
#endif
}

// 32-bit random bits for flat element i of a (B,S) draw
__device__ __forceinline__ uint32_t rand_bits(uint32_t K0, uint32_t K1, uint32_t i) {
#if PARTITIONABLE
    uint32_t x0 = 0u, x1 = i;
    tf2x32(K0, K1, x0, x1);
    return x0 ^ x1;
#else
    const uint32_t half = (BB*SS) / 2;
    if (i < half) { uint32_t x0 = i, x1 = i + half; tf2x32(K0, K1, x0, x1); return x0; }
    else          { uint32_t x0 = i - half, x1 = i; tf2x32(K0, K1, x0, x1); return x1; }
#endif
}

// ---------------- fp32 GEMM: C = A[M,K] @ Bw[N,K]^T (+D) (+bias[n]) ----------------
// 128x128 tile, Kc=16, 256 threads, 8x8 micro-tile, double-buffered smem.
// All M,N multiples of 128; K multiple of 16. D may alias C (in-place add).
__global__ __launch_bounds__(256) void gemm128(
    const float* __restrict__ A, const float* __restrict__ Bw,
    float* C, const float* D, const float* __restrict__ bias,
    int M, int N, int K)
{
    __shared__ float As[2][16][128];
    __shared__ float Bs[2][16][128];
    const int tid = threadIdx.x;
    const int bm = blockIdx.y << 7;
    const int bn = blockIdx.x << 7;

    const int r0 = tid >> 2;            // 0..63
    const int kq = (tid & 3) << 2;      // 0,4,8,12

    const float* Ap0 = A  + (size_t)(bm + r0)      * K + kq;
    const float* Ap1 = A  + (size_t)(bm + r0 + 64) * K + kq;
    const float* Bp0 = Bw + (size_t)(bn + r0)      * K + kq;
    const float* Bp1 = Bw + (size_t)(bn + r0 + 64) * K + kq;

    const int tm = (tid >> 4) << 3;     // row micro-offset
    const int tn = (tid & 15) << 3;     // col micro-offset

    float acc[8][8];
#pragma unroll
    for (int i = 0; i < 8; ++i)
#pragma unroll
        for (int j = 0; j < 8; ++j) acc[i][j] = 0.f;

    const int nk = K >> 4;

    float4 a0 = *(const float4*)Ap0;
    float4 a1 = *(const float4*)Ap1;
    float4 b0 = *(const float4*)Bp0;
    float4 b1 = *(const float4*)Bp1;

    int cur = 0;
    As[0][kq+0][r0]    = a0.x; As[0][kq+1][r0]    = a0.y; As[0][kq+2][r0]    = a0.z; As[0][kq+3][r0]    = a0.w;
    As[0][kq+0][r0+64] = a1.x; As[0][kq+1][r0+64] = a1.y; As[0][kq+2][r0+64] = a1.z; As[0][kq+3][r0+64] = a1.w;
    Bs[0][kq+0][r0]    = b0.x; Bs[0][kq+1][r0]    = b0.y; Bs[0][kq+2][r0]    = b0.z; Bs[0][kq+3][r0]    = b0.w;
    Bs[0][kq+0][r0+64] = b1.x; Bs[0][kq+1][r0+64] = b1.y; Bs[0][kq+2][r0+64] = b1.z; Bs[0][kq+3][r0+64] = b1.w;
    __syncthreads();

    for (int kt = 0; kt < nk; ++kt) {
        const bool has_next = (kt + 1 < nk);
        if (has_next) {
            const int off = (kt + 1) << 4;
            a0 = *(const float4*)(Ap0 + off);
            a1 = *(const float4*)(Ap1 + off);
            b0 = *(const float4*)(Bp0 + off);
            b1 = *(const float4*)(Bp1 + off);
        }
#pragma unroll
        for (int kk = 0; kk < 16; ++kk) {
            const float4 x0 = *(const float4*)&As[cur][kk][tm];
            const float4 x1 = *(const float4*)&As[cur][kk][tm + 4];
            const float4 y0 = *(const float4*)&Bs[cur][kk][tn];
            const float4 y1 = *(const float4*)&Bs[cur][kk][tn + 4];
            const float av[8] = {x0.x,x0.y,x0.z,x0.w,x1.x,x1.y,x1.z,x1.w};
            const float bv[8] = {y0.x,y0.y,y0.z,y0.w,y1.x,y1.y,y1.z,y1.w};
#pragma unroll
            for (int i = 0; i < 8; ++i)
#pragma unroll
                for (int j = 0; j < 8; ++j)
                    acc[i][j] = fmaf(av[i], bv[j], acc[i][j]);
        }
        if (has_next) {
            const int nxt = cur ^ 1;
            As[nxt][kq+0][r0]    = a0.x; As[nxt][kq+1][r0]    = a0.y; As[nxt][kq+2][r0]    = a0.z; As[nxt][kq+3][r0]    = a0.w;
            As[nxt][kq+0][r0+64] = a1.x; As[nxt][kq+1][r0+64] = a1.y; As[nxt][kq+2][r0+64] = a1.z; As[nxt][kq+3][r0+64] = a1.w;
            Bs[nxt][kq+0][r0]    = b0.x; Bs[nxt][kq+1][r0]    = b0.y; Bs[nxt][kq+2][r0]    = b0.z; Bs[nxt][kq+3][r0]    = b0.w;
            Bs[nxt][kq+0][r0+64] = b1.x; Bs[nxt][kq+1][r0+64] = b1.y; Bs[nxt][kq+2][r0+64] = b1.z; Bs[nxt][kq+3][r0+64] = b1.w;
            __syncthreads();
            cur = nxt;
        }
    }

#pragma unroll
    for (int i = 0; i < 8; ++i) {
        const size_t row = (size_t)(bm + tm + i);
        float* Cp = C + row * N + bn + tn;
        const float* Dp = D ? (D + row * N + bn + tn) : nullptr;
#pragma unroll
        for (int j4 = 0; j4 < 2; ++j4) {
            float4 v = make_float4(acc[i][j4*4+0], acc[i][j4*4+1],
                                   acc[i][j4*4+2], acc[i][j4*4+3]);
            if (Dp) {
                const float4 d = *(const float4*)(Dp + j4*4);
                v.x += d.x; v.y += d.y; v.z += d.z; v.w += d.w;
            }
            if (bias) {
                const float4 d = *(const float4*)(bias + bn + tn + j4*4);
                v.x += d.x; v.y += d.y; v.z += d.z; v.w += d.w;
            }
            *(float4*)(Cp + j4*4) = v;
        }
    }
}

// ---------------- prep kernels ----------------
__global__ void init_misc(const float* __restrict__ ebih, const float* __restrict__ ebhh,
                          const float* __restrict__ dbih, const float* __restrict__ dbhh)
{
    const int t = blockIdx.x * blockDim.x + threadIdx.x;
    if (t < G4) { g_bias_enc[t] = ebih[t] + ebhh[t]; g_bias_dec[t] = dbih[t] + dbhh[t]; }
    if (t < BB*SS) g_mask[t] = 0;
    if (t < BB*HH) { g_h[t] = 0.f; g_c[t] = 0.f; }
}

__global__ void gather_x(const int* __restrict__ input, const float* __restrict__ emb)
{
    const int E4 = EE / 4;
    const int t = blockIdx.x * blockDim.x + threadIdx.x;
    if (t >= SS * BB * E4) return;
    const int e4 = t % E4;
    const int r  = t / E4;      // r = s*BB + b
    const int b  = r % BB;
    const int s  = r / BB;
    const int tok = input[b * SS + s];
    ((float4*)g_X)[(size_t)r * E4 + e4] = ((const float4*)emb)[(size_t)tok * E4 + e4];
}

__device__ __forceinline__ float sigm(float x) { return 1.f / (1.f + expf(-x)); }

// torch gate order i,f,g,o over [4H]
__global__ __launch_bounds__(256) void lstm_cell(const float* __restrict__ gates,
                                                 int sIdx, int writeEnc)
{
    const int t = blockIdx.x * blockDim.x + threadIdx.x;  // over B*H
    const int b = t >> 9;
    const int j = t & (HH - 1);
    const float* gb = gates + (size_t)b * G4;
    const float xi = gb[j];
    const float xf = gb[HH + j];
    const float xg = gb[2*HH + j];
    const float xo = gb[3*HH + j];
    const float cn = sigm(xf) * g_c[t] + sigm(xi) * tanhf(xg);
    const float hn = sigm(xo) * tanhf(cn);
    g_c[t] = cn;
    g_h[t] = hn;
    if (writeEnc) g_enc[((size_t)b * SS + sIdx) * HH + j] = hn;
}

// decoder init: c0 = final encoder h; h0 = 0
__global__ void dec_init()
{
    const int t = blockIdx.x * blockDim.x + threadIdx.x;
    if (t < BB*HH) { g_c[t] = g_h[t]; g_h[t] = 0.f; }
}

// ---------------- fused scores + log_softmax + categorical + mask ----------------
// one block per batch row b; 256 threads (8 warps)
__global__ __launch_bounds__(256) void score_sample(
    const float* __restrict__ vt, float* probs, float* tour, int step)
{
    const int b = blockIdx.x;
    const int tid = threadIdx.x;
    const int wid = tid >> 5, lane = tid & 31;
    __shared__ float b2s[WW];
    __shared__ float vts[WW];
    __shared__ float sc[SS];
    __shared__ float smm[SS];
    __shared__ float smv[SS];
    __shared__ float red[2];

    b2s[tid] = g_blend2[b * WW + tid];
    vts[tid] = vt[tid];
    __syncthreads();

    // scores[s] = sum_w vt[w] * tanh(blend1[b,s,w] + blend2[b,w]); warp per s
    for (int s = wid; s < SS; s += 8) {
        const float* row = g_blend1 + ((size_t)b * SS + s) * WW;
        float a = 0.f;
#pragma unroll
        for (int w = lane; w < WW; w += 32)
            a += vts[w] * tanhf(row[w] + b2s[w]);
        a += __shfl_down_sync(0xffffffffu, a, 16);
        a += __shfl_down_sync(0xffffffffu, a,  8);
        a += __shfl_down_sync(0xffffffffu, a,  4);
        a += __shfl_down_sync(0xffffffffu, a,  2);
        a += __shfl_down_sync(0xffffffffu, a,  1);
        if (lane == 0) sc[s] = a;
    }
    __syncthreads();

    if (tid < SS) {
        const float sm_ = g_mask[b * SS + tid] ? -100000.0f : sc[tid];
        uint32_t K0, K1;
        derive_key(step, K0, K1);
        const uint32_t bits = rand_bits(K0, K1, (uint32_t)(b * SS + tid));
        // jax uniform(tiny, 1): bitcast trick then clamp
        float u = __uint_as_float((bits >> 9) | 0x3f800000u) - 1.0f;
        u = u + 1.17549435e-38f;
        if (u < 1.17549435e-38f) u = 1.17549435e-38f;
        const float g = -logf(-logf(u));
        smm[tid] = sm_;
        smv[tid] = sm_ + g;
    }
    __syncthreads();

    if (tid == 0) {
        float best = smv[0]; int bi = 0; float mx = smm[0];
        for (int s = 1; s < SS; ++s) {
            if (smv[s] > best) { best = smv[s]; bi = s; }   // first-max tie-break (jnp.argmax)
            if (smm[s] > mx) mx = smm[s];
        }
        float sum = 0.f;
        for (int s = 0; s < SS; ++s) sum += expf(smm[s] - mx);
        red[0] = mx; red[1] = logf(sum);
        g_mask[b * SS + bi] = 1;
        if (tour) tour[(size_t)b * LL + step] = (float)bi;
    }
    __syncthreads();

    if (tid < SS && probs) {
        probs[((size_t)b * LL + step) * SS + tid] = (smm[tid] - red[0]) - red[1];
    }
}

// ---------------- launch ----------------
extern "C" void kernel_launch(void* const* d_in, const int* in_sizes, int n_in,
                              void* d_out, int out_size)
{
    if (n_in < 13) return;
    const int*   input = (const int*)  d_in[0];
    const float* emb   = (const float*)d_in[1];
    const float* eWih  = (const float*)d_in[2];
    const float* eWhh  = (const float*)d_in[3];
    const float* ebih  = (const float*)d_in[4];
    const float* ebhh  = (const float*)d_in[5];
    /* d_in[6] = dec_Wih : unused (decoder input is all zeros) */
    const float* dWhh  = (const float*)d_in[7];
    const float* dbih  = (const float*)d_in[8];
    const float* dbhh  = (const float*)d_in[9];
    const float* W1    = (const float*)d_in[10];
    const float* W2    = (const float*)d_in[11];
    const float* vt    = (const float*)d_in[12];

    float *pX, *pGates, *pEnc, *pB1, *pGd, *pH, *pB2, *pBE, *pBD;
    cudaGetSymbolAddress((void**)&pX,    g_X);
    cudaGetSymbolAddress((void**)&pGates,g_gates);
    cudaGetSymbolAddress((void**)&pEnc,  g_enc);
    cudaGetSymbolAddress((void**)&pB1,   g_blend1);
    cudaGetSymbolAddress((void**)&pGd,   g_gdec);
    cudaGetSymbolAddress((void**)&pH,    g_h);
    cudaGetSymbolAddress((void**)&pB2,   g_blend2);
    cudaGetSymbolAddress((void**)&pBE,   g_bias_enc);
    cudaGetSymbolAddress((void**)&pBD,   g_bias_dec);

    const size_t np = (size_t)BB * LL * SS;   // 5,120,000 probs
    const size_t nt = (size_t)BB * LL;        //   102,400 tour
    float* probs = ((size_t)out_size >= np)      ? (float*)d_out        : nullptr;
    float* tour  = ((size_t)out_size >= np + nt) ? ((float*)d_out + np) : nullptr;

    // prep: biases, zero h/c/mask, gather embeddings
    init_misc<<<4096, 256>>>(ebih, ebhh, dbih, dbhh);
    gather_x<<<25600, 256>>>(input, emb);

    // encoder input projections for ALL timesteps in one big GEMM:
    // g_gates[s][b][:] = X[s][b][:] @ enc_Wih^T + (bih+bhh)
    gemm128<<<dim3(16, 800), 256>>>(pX, eWih, pGates, nullptr, pBE, SS*BB, G4, EE);

    // encoder recurrence
    for (int s = 0; s < SS; ++s) {
        float* gs = pGates + (size_t)s * BB * G4;
        gemm128<<<dim3(16, 16), 256>>>(pH, eWhh, gs, gs, nullptr, BB, G4, HH); // += h@Whh^T
        lstm_cell<<<4096, 256>>>(gs, s, 1);
    }

    // decoder init: c0 = enc_seq[-1] (= final h), h0 = 0
    dec_init<<<4096, 256>>>();

    // blend1 = enc_states @ W1^T  (loop-invariant)
    gemm128<<<dim3(2, 800), 256>>>(pEnc, W1, pB1, nullptr, nullptr, BB*SS, WW, HH);

    // decoder: x is zero -> gates = bias + h@Whh^T
    for (int k = 0; k < LL; ++k) {
        gemm128<<<dim3(16, 16), 256>>>(pH, dWhh, pGd, nullptr, pBD, BB, G4, HH);
        lstm_cell<<<4096, 256>>>(pGd, 0, 0);
        gemm128<<<dim3(2, 16), 256>>>(pH, W2, pB2, nullptr, nullptr, BB, WW, HH); // blend2
        score_sample<<<BB, 256>>>(vt, probs, tour, k);
    }
}

// round 12
// speedup vs baseline: 1.1152x; 1.1152x over previous
#include <cuda_runtime.h>
#include <cstdint>
#include <math.h>

// Problem dims (fixed by the reference)
#define BB 2048
#define SS 50
#define EE 256
#define HH 512
#define G4 (4*HH)       // 2048
#define WW 256
#define LL 50
#define GCAT (G4 + WW)  // 2304 : [dec gates | blend2]

#define PARTITIONABLE 1

// ---------------- scratch (static device globals; no allocation) ----------------
__device__ __align__(16) float g_X[SS*BB*EE];        // gathered embeddings, [s][b][e]
__device__ __align__(16) float g_gates[SS*BB*G4];    // encoder pre-activations
__device__ __align__(16) float g_enc[BB*SS*HH];      // encoder hidden states [b][s][h]
__device__ __align__(16) float g_blend1[BB*SS*WW];   // W1 @ enc_states, [b][s][w]
__device__ __align__(16) float g_gdec[BB*GCAT];      // decoder [gates | blend2]
__device__ __align__(16) float g_h[BB*HH];
__device__ __align__(16) float g_c[BB*HH];
__device__ __align__(16) float g_bias_enc[G4];
__device__ __align__(16) float g_bias_dec[G4];
__device__ __align__(16) float g_Wcat[GCAT*HH];      // [dec_Whh ; W2]
__device__ __align__(16) float g_bias_cat[GCAT];     // [bias_dec ; 0]
__device__ unsigned char g_mask[BB*SS];

// ---------------- Threefry-2x32-20 (exact JAX algorithm) ----------------
__device__ __forceinline__ uint32_t rotl32(uint32_t v, int r) {
    return (v << r) | (v >> (32 - r));
}

__device__ __forceinline__ void tf2x32(uint32_t k0, uint32_t k1,
                                       uint32_t& x0, uint32_t& x1) {
    const uint32_t ks2 = k0 ^ k1 ^ 0x1BD11BDAu;
    x0 += k0; x1 += k1;
    x0 += x1; x1 = rotl32(x1, 13); x1 ^= x0;
    x0 += x1; x1 = rotl32(x1, 15); x1 ^= x0;
    x0 += x1; x1 = rotl32(x1, 26); x1 ^= x0;
    x0 += x1; x1 = rotl32(x1,  6); x1 ^= x0;
    x0 += k1; x1 += ks2 + 1u;
    x0 += x1; x1 = rotl32(x1, 17); x1 ^= x0;
    x0 += x1; x1 = rotl32(x1, 29); x1 ^= x0;
    x0 += x1; x1 = rotl32(x1, 16); x1 ^= x0;
    x0 += x1; x1 = rotl32(x1, 24); x1 ^= x0;
    x0 += ks2; x1 += k0 + 2u;
    x0 += x1; x1 = rotl32(x1, 13); x1 ^= x0;
    x0 += x1; x1 = rotl32(x1, 15); x1 ^= x0;
    x0 += x1; x1 = rotl32(x1, 26); x1 ^= x0;
    x0 += x1; x1 = rotl32(x1,  6); x1 ^= x0;
    x0 += k0; x1 += k1 + 3u;
    x0 += x1; x1 = rotl32(x1, 17); x1 ^= x0;
    x0 += x1; x1 = rotl32(x1, 29); x1 ^= x0;
    x0 += x1; x1 = rotl32(x1, 16); x1 ^= x0;
    x0 += x1; x1 = rotl32(x1, 24); x1 ^= x0;
    x0 += k1; x1 += ks2 + 4u;
    x0 += x1; x1 = rotl32(x1, 13); x1 ^= x0;
    x0 += x1; x1 = rotl32(x1, 15); x1 ^= x0;
    x0 += x1; x1 = rotl32(x1, 26); x1 ^= x0;
    x0 += x1; x1 = rotl32(x1,  6); x1 ^= x0;
    x0 += ks2; x1 += k0 + 5u;
}

__device__ __forceinline__ void derive_key(int step, uint32_t& K0, uint32_t& K1) {
#if PARTITIONABLE
    uint32_t a = 0u, b = (uint32_t)step;
    tf2x32(0u, 42u, a, b);
    K0 = a; K1 = b;
#else
    const int la = (step < 25) ? 2*step : 2*step - 50;
    uint32_t a0 = (uint32_t)la,     a1 = (uint32_t)(la + 50);
    uint32_t b0 = (uint32_t)(la+1), b1 = (uint32_t)(la + 51);
    tf2x32(0u, 42u, a0, a1);
    tf2x32(0u, 42u, b0, b1);
    if (step < 25) { K0 = a0; K1 = b0; } else { K0 = a1; K1 = b1; }
#endif
}

__device__ __forceinline__ uint32_t rand_bits(uint32_t K0, uint32_t K1, uint32_t i) {
#if PARTITIONABLE
    uint32_t x0 = 0u, x1 = i;
    tf2x32(K0, K1, x0, x1);
    return x0 ^ x1;
#else
    const uint32_t half = (BB*SS) / 2;
    if (i < half) { uint32_t x0 = i, x1 = i + half; tf2x32(K0, K1, x0, x1); return x0; }
    else          { uint32_t x0 = i - half, x1 = i; tf2x32(K0, K1, x0, x1); return x1; }
#endif
}

// ---------------- fp32 GEMM with packed f32x2 FMA ----------------
// C[M,N] = A[M,K] @ Bw[N,K]^T (+D) (+bias[n]); 128x128 tile, Kc=16,
// 256 threads, 8x8 micro-tile as 8x4 packed-f32x2 accumulators, double buffered.
// M,N multiples of 128; K multiple of 16. D may alias C.
__global__ __launch_bounds__(256) void gemm128(
    const float* __restrict__ A, const float* __restrict__ Bw,
    float* C, const float* D, const float* __restrict__ bias,
    int M, int N, int K)
{
    __shared__ float As[2][16][128];
    __shared__ float Bs[2][16][128];
    const int tid = threadIdx.x;
    const int bm = blockIdx.y << 7;
    const int bn = blockIdx.x << 7;

    const int r0 = tid >> 2;            // 0..63
    const int kq = (tid & 3) << 2;      // 0,4,8,12

    const float* Ap0 = A  + (size_t)(bm + r0)      * K + kq;
    const float* Ap1 = A  + (size_t)(bm + r0 + 64) * K + kq;
    const float* Bp0 = Bw + (size_t)(bn + r0)      * K + kq;
    const float* Bp1 = Bw + (size_t)(bn + r0 + 64) * K + kq;

    const int tm = (tid >> 4) << 3;     // row micro-offset
    const int tn = (tid & 15) << 3;     // col micro-offset (multiple of 8 -> 32B aligned)

    // packed accumulators: acc2[i][j2] holds cols (tn+2*j2, tn+2*j2+1) for row tm+i
    unsigned long long acc2[8][4];
#pragma unroll
    for (int i = 0; i < 8; ++i)
#pragma unroll
        for (int j = 0; j < 4; ++j) acc2[i][j] = 0ull;

    const int nk = K >> 4;

    float4 a0 = *(const float4*)Ap0;
    float4 a1 = *(const float4*)Ap1;
    float4 b0 = *(const float4*)Bp0;
    float4 b1 = *(const float4*)Bp1;

    int cur = 0;
    As[0][kq+0][r0]    = a0.x; As[0][kq+1][r0]    = a0.y; As[0][kq+2][r0]    = a0.z; As[0][kq+3][r0]    = a0.w;
    As[0][kq+0][r0+64] = a1.x; As[0][kq+1][r0+64] = a1.y; As[0][kq+2][r0+64] = a1.z; As[0][kq+3][r0+64] = a1.w;
    Bs[0][kq+0][r0]    = b0.x; Bs[0][kq+1][r0]    = b0.y; Bs[0][kq+2][r0]    = b0.z; Bs[0][kq+3][r0]    = b0.w;
    Bs[0][kq+0][r0+64] = b1.x; Bs[0][kq+1][r0+64] = b1.y; Bs[0][kq+2][r0+64] = b1.z; Bs[0][kq+3][r0+64] = b1.w;
    __syncthreads();

    for (int kt = 0; kt < nk; ++kt) {
        const bool has_next = (kt + 1 < nk);
        if (has_next) {
            const int off = (kt + 1) << 4;
            a0 = *(const float4*)(Ap0 + off);
            a1 = *(const float4*)(Ap1 + off);
            b0 = *(const float4*)(Bp0 + off);
            b1 = *(const float4*)(Bp1 + off);
        }
#pragma unroll
        for (int kk = 0; kk < 16; ++kk) {
            const float4 x0 = *(const float4*)&As[cur][kk][tm];
            const float4 x1 = *(const float4*)&As[cur][kk][tm + 4];
            const unsigned long long* bp =
                (const unsigned long long*)&Bs[cur][kk][tn];
            unsigned long long bpk[4];
            bpk[0] = bp[0]; bpk[1] = bp[1]; bpk[2] = bp[2]; bpk[3] = bp[3];
            const float av[8] = {x0.x,x0.y,x0.z,x0.w,x1.x,x1.y,x1.z,x1.w};
#pragma unroll
            for (int i = 0; i < 8; ++i) {
                unsigned long long a2;
                const unsigned int ai = __float_as_uint(av[i]);
                asm("mov.b64 %0, {%1, %2};" : "=l"(a2) : "r"(ai), "r"(ai));
#pragma unroll
                for (int j = 0; j < 4; ++j) {
                    asm("fma.rn.f32x2 %0, %1, %2, %0;"
                        : "+l"(acc2[i][j]) : "l"(a2), "l"(bpk[j]));
                }
            }
        }
        if (has_next) {
            const int nxt = cur ^ 1;
            As[nxt][kq+0][r0]    = a0.x; As[nxt][kq+1][r0]    = a0.y; As[nxt][kq+2][r0]    = a0.z; As[nxt][kq+3][r0]    = a0.w;
            As[nxt][kq+0][r0+64] = a1.x; As[nxt][kq+1][r0+64] = a1.y; As[nxt][kq+2][r0+64] = a1.z; As[nxt][kq+3][r0+64] = a1.w;
            Bs[nxt][kq+0][r0]    = b0.x; Bs[nxt][kq+1][r0]    = b0.y; Bs[nxt][kq+2][r0]    = b0.z; Bs[nxt][kq+3][r0]    = b0.w;
            Bs[nxt][kq+0][r0+64] = b1.x; Bs[nxt][kq+1][r0+64] = b1.y; Bs[nxt][kq+2][r0+64] = b1.z; Bs[nxt][kq+3][r0+64] = b1.w;
            __syncthreads();
            cur = nxt;
        }
    }

#pragma unroll
    for (int i = 0; i < 8; ++i) {
        float accf[8];
#pragma unroll
        for (int j = 0; j < 4; ++j) {
            unsigned int lo, hi;
            asm("mov.b64 {%0, %1}, %2;" : "=r"(lo), "=r"(hi) : "l"(acc2[i][j]));
            accf[2*j]   = __uint_as_float(lo);
            accf[2*j+1] = __uint_as_float(hi);
        }
        const size_t row = (size_t)(bm + tm + i);
        float* Cp = C + row * N + bn + tn;
        const float* Dp = D ? (D + row * N + bn + tn) : nullptr;
#pragma unroll
        for (int j4 = 0; j4 < 2; ++j4) {
            float4 v = make_float4(accf[j4*4+0], accf[j4*4+1],
                                   accf[j4*4+2], accf[j4*4+3]);
            if (Dp) {
                const float4 d = *(const float4*)(Dp + j4*4);
                v.x += d.x; v.y += d.y; v.z += d.z; v.w += d.w;
            }
            if (bias) {
                const float4 d = *(const float4*)(bias + bn + tn + j4*4);
                v.x += d.x; v.y += d.y; v.z += d.z; v.w += d.w;
            }
            *(float4*)(Cp + j4*4) = v;
        }
    }
}

// ---------------- prep kernels ----------------
__global__ void init_misc(const float* __restrict__ ebih, const float* __restrict__ ebhh,
                          const float* __restrict__ dbih, const float* __restrict__ dbhh)
{
    const int t = blockIdx.x * blockDim.x + threadIdx.x;
    if (t < G4) { g_bias_enc[t] = ebih[t] + ebhh[t]; g_bias_dec[t] = dbih[t] + dbhh[t]; }
    if (t < GCAT) g_bias_cat[t] = (t < G4) ? (dbih[t] + dbhh[t]) : 0.f;
    if (t < BB*SS) g_mask[t] = 0;
    if (t < BB*HH) { g_h[t] = 0.f; g_c[t] = 0.f; }
}

// build Wcat = [dec_Whh (2048 rows) ; W2 (256 rows)], each row HH floats
__global__ void prep_wcat(const float* __restrict__ dWhh, const float* __restrict__ W2)
{
    const int H4 = HH / 4;
    const int t = blockIdx.x * blockDim.x + threadIdx.x;
    if (t >= GCAT * H4) return;
    const int row = t / H4;
    const int c4  = t % H4;
    float4 v;
    if (row < G4) v = ((const float4*)dWhh)[(size_t)row * H4 + c4];
    else          v = ((const float4*)W2)  [(size_t)(row - G4) * H4 + c4];
    ((float4*)g_Wcat)[(size_t)row * H4 + c4] = v;
}

__global__ void gather_x(const int* __restrict__ input, const float* __restrict__ emb)
{
    const int E4 = EE / 4;
    const int t = blockIdx.x * blockDim.x + threadIdx.x;
    if (t >= SS * BB * E4) return;
    const int e4 = t % E4;
    const int r  = t / E4;      // r = s*BB + b
    const int b  = r % BB;
    const int s  = r / BB;
    const int tok = input[b * SS + s];
    ((float4*)g_X)[(size_t)r * E4 + e4] = ((const float4*)emb)[(size_t)tok * E4 + e4];
}

__device__ __forceinline__ float sigm(float x) { return 1.f / (1.f + expf(-x)); }

// torch gate order i,f,g,o. gates row stride parameterized; rowStride=0 broadcasts
// one vector (used for decoder step 0 where gates == bias exactly).
__global__ __launch_bounds__(256) void lstm_cell(const float* __restrict__ gates,
                                                 int rowStride, int sIdx, int writeEnc)
{
    const int t = blockIdx.x * blockDim.x + threadIdx.x;  // over B*H
    const int b = t >> 9;
    const int j = t & (HH - 1);
    const float* gb = gates + (size_t)b * rowStride;
    const float xi = gb[j];
    const float xf = gb[HH + j];
    const float xg = gb[2*HH + j];
    const float xo = gb[3*HH + j];
    const float cn = sigm(xf) * g_c[t] + sigm(xi) * tanhf(xg);
    const float hn = sigm(xo) * tanhf(cn);
    g_c[t] = cn;
    g_h[t] = hn;
    if (writeEnc) g_enc[((size_t)b * SS + sIdx) * HH + j] = hn;
}

// decoder init: c0 = final encoder h; h0 = 0
__global__ void dec_init()
{
    const int t = blockIdx.x * blockDim.x + threadIdx.x;
    if (t < BB*HH) { g_c[t] = g_h[t]; g_h[t] = 0.f; }
}

// ---------------- fused scores + log_softmax + categorical + mask ----------------
__global__ __launch_bounds__(256) void score_sample(
    const float* __restrict__ blend2, int b2stride,
    const float* __restrict__ vt, float* probs, float* tour, int step)
{
    const int b = blockIdx.x;
    const int tid = threadIdx.x;
    const int wid = tid >> 5, lane = tid & 31;
    __shared__ float b2s[WW];
    __shared__ float vts[WW];
    __shared__ float sc[SS];
    __shared__ float smm[SS];
    __shared__ float smv[SS];
    __shared__ float red[2];

    b2s[tid] = blend2[(size_t)b * b2stride + tid];
    vts[tid] = vt[tid];
    __syncthreads();

    for (int s = wid; s < SS; s += 8) {
        const float* row = g_blend1 + ((size_t)b * SS + s) * WW;
        float a = 0.f;
#pragma unroll
        for (int w = lane; w < WW; w += 32)
            a += vts[w] * tanhf(row[w] + b2s[w]);
        a += __shfl_down_sync(0xffffffffu, a, 16);
        a += __shfl_down_sync(0xffffffffu, a,  8);
        a += __shfl_down_sync(0xffffffffu, a,  4);
        a += __shfl_down_sync(0xffffffffu, a,  2);
        a += __shfl_down_sync(0xffffffffu, a,  1);
        if (lane == 0) sc[s] = a;
    }
    __syncthreads();

    if (tid < SS) {
        const float sm_ = g_mask[b * SS + tid] ? -100000.0f : sc[tid];
        uint32_t K0, K1;
        derive_key(step, K0, K1);
        const uint32_t bits = rand_bits(K0, K1, (uint32_t)(b * SS + tid));
        float u = __uint_as_float((bits >> 9) | 0x3f800000u) - 1.0f;
        u = u + 1.17549435e-38f;
        if (u < 1.17549435e-38f) u = 1.17549435e-38f;
        const float g = -logf(-logf(u));
        smm[tid] = sm_;
        smv[tid] = sm_ + g;
    }
    __syncthreads();

    if (tid == 0) {
        float best = smv[0]; int bi = 0; float mx = smm[0];
        for (int s = 1; s < SS; ++s) {
            if (smv[s] > best) { best = smv[s]; bi = s; }
            if (smm[s] > mx) mx = smm[s];
        }
        float sum = 0.f;
        for (int s = 0; s < SS; ++s) sum += expf(smm[s] - mx);
        red[0] = mx; red[1] = logf(sum);
        g_mask[b * SS + bi] = 1;
        if (tour) tour[(size_t)b * LL + step] = (float)bi;
    }
    __syncthreads();

    if (tid < SS && probs) {
        probs[((size_t)b * LL + step) * SS + tid] = (smm[tid] - red[0]) - red[1];
    }
}

// ---------------- launch ----------------
extern "C" void kernel_launch(void* const* d_in, const int* in_sizes, int n_in,
                              void* d_out, int out_size)
{
    if (n_in < 13) return;
    const int*   input = (const int*)  d_in[0];
    const float* emb   = (const float*)d_in[1];
    const float* eWih  = (const float*)d_in[2];
    const float* eWhh  = (const float*)d_in[3];
    const float* ebih  = (const float*)d_in[4];
    const float* ebhh  = (const float*)d_in[5];
    /* d_in[6] = dec_Wih : unused (decoder input is all zeros) */
    const float* dWhh  = (const float*)d_in[7];
    const float* dbih  = (const float*)d_in[8];
    const float* dbhh  = (const float*)d_in[9];
    const float* W1    = (const float*)d_in[10];
    const float* W2    = (const float*)d_in[11];
    const float* vt    = (const float*)d_in[12];

    float *pX, *pGates, *pEnc, *pB1, *pGd, *pH, *pBE, *pBD, *pWcat, *pBC;
    cudaGetSymbolAddress((void**)&pX,    g_X);
    cudaGetSymbolAddress((void**)&pGates,g_gates);
    cudaGetSymbolAddress((void**)&pEnc,  g_enc);
    cudaGetSymbolAddress((void**)&pB1,   g_blend1);
    cudaGetSymbolAddress((void**)&pGd,   g_gdec);
    cudaGetSymbolAddress((void**)&pH,    g_h);
    cudaGetSymbolAddress((void**)&pBE,   g_bias_enc);
    cudaGetSymbolAddress((void**)&pBD,   g_bias_dec);
    cudaGetSymbolAddress((void**)&pWcat, g_Wcat);
    cudaGetSymbolAddress((void**)&pBC,   g_bias_cat);

    const size_t np = (size_t)BB * LL * SS;
    const size_t nt = (size_t)BB * LL;
    float* probs = ((size_t)out_size >= np)      ? (float*)d_out        : nullptr;
    float* tour  = ((size_t)out_size >= np + nt) ? ((float*)d_out + np) : nullptr;

    // prep
    init_misc<<<4096, 256>>>(ebih, ebhh, dbih, dbhh);
    prep_wcat<<<(GCAT*(HH/4) + 255)/256, 256>>>(dWhh, W2);
    gather_x<<<25600, 256>>>(input, emb);

    // encoder input projections, all timesteps in one GEMM
    gemm128<<<dim3(16, 800), 256>>>(pX, eWih, pGates, nullptr, pBE, SS*BB, G4, EE);

    // encoder recurrence
    for (int s = 0; s < SS; ++s) {
        float* gs = pGates + (size_t)s * BB * G4;
        gemm128<<<dim3(16, 16), 256>>>(pH, eWhh, gs, gs, nullptr, BB, G4, HH);
        lstm_cell<<<4096, 256>>>(gs, G4, s, 1);
    }

    // decoder init: c0 = enc_seq[-1], h0 = 0
    dec_init<<<4096, 256>>>();

    // blend1 = enc_states @ W1^T (loop-invariant)
    gemm128<<<dim3(2, 800), 256>>>(pEnc, W1, pB1, nullptr, nullptr, BB*SS, WW, HH);

    // decoder:
    // step-0 cell reads gates == bias exactly (h0 = 0, dec_in = 0) via stride-0
    lstm_cell<<<4096, 256>>>(pBD, 0, 0, 0);                       // -> h_1
    for (int k = 0; k < LL; ++k) {
        // one wide GEMM: [gates_{k+1} | blend2_k] = h_{k+1} @ [Whh; W2]^T (+bias|0)
        gemm128<<<dim3(18, 16), 256>>>(pH, pWcat, pGd, nullptr, pBC, BB, GCAT, HH);
        score_sample<<<BB, 256>>>(pGd + G4, GCAT, vt, probs, tour, k);
        if (k < LL - 1)
            lstm_cell<<<4096, 256>>>(pGd, GCAT, 0, 0);            // -> h_{k+2}
    }
}